// round 9
// baseline (speedup 1.0000x reference)
#include <cuda_runtime.h>
#include <cuda_fp16.h>
#include <cstdint>

#define NTHR  512     // 256 consumer + 256 producer
#define NCONS 256
#define ET    128
#define XSTR  264     // halves
#define W1STR 136
#define W2STR 96
#define HSTR  136
// byte offsets in dynamic smem
#define B_X0  0            // 67584
#define B_X1  67584        // 67584
#define B_W1  135168       // 69632
#define B_W2  204800       // 24576
#define B_DST 229376       // 2 * 128 * 4
#define SMEMB 230400

// named barrier ids: FULL0=1 FULL1=2 EMPTY0=3 EMPTY1=4 C1=5 C2=6
#define BAR_SYNC(id, cnt)   asm volatile("bar.sync %0, %1;"   :: "r"(id), "r"(cnt) : "memory")
#define BAR_ARRIVE(id, cnt) asm volatile("bar.arrive %0, %1;" :: "r"(id), "r"(cnt) : "memory")

__device__ __forceinline__ uint32_t s2u(const void* p) {
    uint32_t a; asm("{ .reg .u64 t; cvta.to.shared.u64 t, %1; cvt.u32.u64 %0, t; }" : "=r"(a) : "l"(p)); return a;
}
__device__ __forceinline__ void ldsm4(uint32_t a, uint32_t& r0, uint32_t& r1, uint32_t& r2, uint32_t& r3) {
    asm volatile("ldmatrix.sync.aligned.m8n8.x4.shared.b16 {%0,%1,%2,%3}, [%4];"
                 : "=r"(r0), "=r"(r1), "=r"(r2), "=r"(r3) : "r"(a));
}
__device__ __forceinline__ void ldsm4t(uint32_t a, uint32_t& r0, uint32_t& r1, uint32_t& r2, uint32_t& r3) {
    asm volatile("ldmatrix.sync.aligned.m8n8.x4.trans.shared.b16 {%0,%1,%2,%3}, [%4];"
                 : "=r"(r0), "=r"(r1), "=r"(r2), "=r"(r3) : "r"(a));
}
__device__ __forceinline__ void ldsm2t(uint32_t a, uint32_t& r0, uint32_t& r1) {
    asm volatile("ldmatrix.sync.aligned.m8n8.x2.trans.shared.b16 {%0,%1}, [%2];"
                 : "=r"(r0), "=r"(r1) : "r"(a));
}
__device__ __forceinline__ void stsm4(uint32_t a, uint32_t r0, uint32_t r1, uint32_t r2, uint32_t r3) {
    asm volatile("stmatrix.sync.aligned.m8n8.x4.shared.b16 [%0], {%1,%2,%3,%4};"
                 :: "r"(a), "r"(r0), "r"(r1), "r"(r2), "r"(r3) : "memory");
}
__device__ __forceinline__ void mma16816(float* c, const uint32_t* a, const uint32_t* b) {
    asm volatile("mma.sync.aligned.m16n8k16.row.col.f32.f16.f16.f32 "
                 "{%0,%1,%2,%3}, {%4,%5,%6,%7}, {%8,%9}, {%0,%1,%2,%3};"
                 : "+f"(c[0]), "+f"(c[1]), "+f"(c[2]), "+f"(c[3])
                 : "r"(a[0]), "r"(a[1]), "r"(a[2]), "r"(a[3]), "r"(b[0]), "r"(b[1]));
}
__device__ __forceinline__ void red2(float* p, float a, float b) {
    asm volatile("red.global.add.v2.f32 [%0], {%1,%2};" :: "l"(p), "f"(a), "f"(b) : "memory");
}
// 8 fp32 -> 8 fp16, one 16B STS
__device__ __forceinline__ void wr8h(__half* px, int idx, const float* v) {
    uint4 u;
    uint32_t* w = (uint32_t*)&u;
    #pragma unroll
    for (int q = 0; q < 4; q++) {
        __half h0 = __float2half_rn(v[2*q]), h1 = __float2half_rn(v[2*q+1]);
        w[q] = (uint32_t)__half_as_ushort(h0) | ((uint32_t)__half_as_ushort(h1) << 16);
    }
    *(uint4*)(px + idx) = u;
}
// inverse-rotate one rep (8 values)
__device__ __forceinline__ void rot8(const float* p, const float4* rk, float* o) {
    #pragma unroll
    for (int k = 0; k < 4; k++) {
        float x0 = p[2*k], x1 = p[2*k+1];
        o[2*k]   = x0 * rk[k].x + x1 * rk[k].y;
        o[2*k+1] = x0 * rk[k].z + x1 * rk[k].w;
    }
}

__global__ __launch_bounds__(NTHR, 1)
void eq_main(const float* __restrict__ xs, const float* __restrict__ xr,
             const int* __restrict__ ei, const float* __restrict__ dist,
             const float* __restrict__ rot,
             const float* __restrict__ W1, const float* __restrict__ b1,
             const float* __restrict__ W2, const float* __restrict__ b2,
             float* __restrict__ outS, float* __restrict__ outR,
             int E, int n_tiles)
{
    extern __shared__ __align__(16) unsigned char dyn[];
    const uint32_t sb = s2u(dyn);
    __half* sW1 = (__half*)(dyn + B_W1);
    __half* sW2 = (__half*)(dyn + B_W2);
    int*   sDst = (int*)  (dyn + B_DST);

    const int tid = threadIdx.x, lane = tid & 31, wid = tid >> 5;

    // ---- stage weights once (all threads) ----
    for (int i = tid; i < 256 * 128; i += NTHR) {
        int k = i >> 7, n = i & 127;
        sW1[k * W1STR + n] = __float2half_rn(W1[i]);
    }
    for (int i = tid; i < 128 * 96; i += NTHR) {
        int k = i / 96, n = i - k * 96;
        sW2[k * W2STR + n] = __float2half_rn(W2[i]);
    }
    __syncthreads();

    const int t0 = blockIdx.x, gstride = gridDim.x;

    if (wid >= 8) {
        // ================= PRODUCER: 8 warps, 2 threads per edge =================
        const int ptid = tid - NCONS;     // 0..255
        const int pe   = ptid >> 1;       // edge 0..127
        const int part = ptid & 1;
        int i = 0;
        for (int t = t0; t < n_tiles; t += gstride, i++) {
            const int buf = i & 1;
            if (i >= 2) BAR_SYNC(3 + buf, NTHR);        // wait EMPTY[buf]
            __half* X = (__half*)(dyn + (buf ? B_X1 : B_X0));
            const int base = t * ET;
            const int e  = base + pe;
            const int ec = (e < E) ? e : (E - 1);
            float4 rk[4];
            #pragma unroll
            for (int k = 0; k < 4; k++) rk[k] = *(const float4*)(rot + (size_t)ec * 16 + k * 4);
            const int rb = pe * XSTR;
            float tmp[8], in[8];
            if (part == 0) {
                const int dstn = ei[E + ec];
                sDst[buf * ET + pe] = dstn;
                // dst scalars -> cols 0..31
                #pragma unroll
                for (int q = 0; q < 4; q++) {
                    *(float4*)(tmp)     = *(const float4*)(xs + (size_t)dstn * 32 + q * 8);
                    *(float4*)(tmp + 4) = *(const float4*)(xs + (size_t)dstn * 32 + q * 8 + 4);
                    wr8h(X, rb + q * 8, tmp);
                }
                // dst rot reps -> cols 32..95
                #pragma unroll
                for (int j = 0; j < 8; j++) {
                    *(float4*)(in)     = *(const float4*)(xr + (size_t)dstn * 64 + j * 8);
                    *(float4*)(in + 4) = *(const float4*)(xr + (size_t)dstn * 64 + j * 8 + 4);
                    rot8(in, rk, tmp);
                    wr8h(X, rb + 32 + j * 8, tmp);
                }
                // dist[0:32] -> cols 192..223
                #pragma unroll
                for (int q = 0; q < 4; q++) {
                    *(float4*)(tmp)     = *(const float4*)(dist + (size_t)ec * 64 + q * 8);
                    *(float4*)(tmp + 4) = *(const float4*)(dist + (size_t)ec * 64 + q * 8 + 4);
                    wr8h(X, rb + 192 + q * 8, tmp);
                }
            } else {
                const int srcn = ei[ec];
                // src scalars -> cols 96..127
                #pragma unroll
                for (int q = 0; q < 4; q++) {
                    *(float4*)(tmp)     = *(const float4*)(xs + (size_t)srcn * 32 + q * 8);
                    *(float4*)(tmp + 4) = *(const float4*)(xs + (size_t)srcn * 32 + q * 8 + 4);
                    wr8h(X, rb + 96 + q * 8, tmp);
                }
                // src rot reps -> cols 128..191
                #pragma unroll
                for (int j = 0; j < 8; j++) {
                    *(float4*)(in)     = *(const float4*)(xr + (size_t)srcn * 64 + j * 8);
                    *(float4*)(in + 4) = *(const float4*)(xr + (size_t)srcn * 64 + j * 8 + 4);
                    rot8(in, rk, tmp);
                    wr8h(X, rb + 128 + j * 8, tmp);
                }
                // dist[32:64] -> cols 224..255
                #pragma unroll
                for (int q = 0; q < 4; q++) {
                    *(float4*)(tmp)     = *(const float4*)(dist + (size_t)ec * 64 + 32 + q * 8);
                    *(float4*)(tmp + 4) = *(const float4*)(dist + (size_t)ec * 64 + 32 + q * 8 + 4);
                    wr8h(X, rb + 224 + q * 8, tmp);
                }
            }
            BAR_ARRIVE(1 + buf, NTHR);                  // signal FULL[buf]
        }
    } else {
        // ================= CONSUMER: 8 warps, warp tile 64 x 32 =================
        const int mw = wid >> 2, nw = wid & 3;          // mw: 0..1 (64 rows), nw: 0..3
        const int lr = lane & 15, lc = (lane >> 4) << 3;
        const int g  = lane >> 2, tc = (lane & 3) * 2;
        const uint32_t w1B = sb + B_W1, w2B = sb + B_W2;

        int i = 0;
        for (int t = t0; t < n_tiles; t += gstride, i++) {
            const int buf = i & 1;
            const int base = t * ET;
            const uint32_t xB = sb + (buf ? B_X1 : B_X0);

            BAR_SYNC(1 + buf, NTHR);                    // wait FULL[buf]

            // ---------- GEMM1: 128 x 128 x 256 (this warp: 64 x 32) ----------
            float acc[4][4][4] = {};
            for (int ks = 0; ks < 16; ks++) {
                const int k0 = ks * 16;
                uint32_t b[4][2];
                ldsm4t(w1B + (uint32_t)(((k0 + lr) * W1STR + nw * 32 + lc) * 2),
                       b[0][0], b[0][1], b[1][0], b[1][1]);
                ldsm4t(w1B + (uint32_t)(((k0 + lr) * W1STR + nw * 32 + 16 + lc) * 2),
                       b[2][0], b[2][1], b[3][0], b[3][1]);
                uint32_t A[4][4];
                #pragma unroll
                for (int mi = 0; mi < 4; mi++)
                    ldsm4(xB + (uint32_t)(((mw * 64 + mi * 16 + lr) * XSTR + k0 + lc) * 2),
                          A[mi][0], A[mi][1], A[mi][2], A[mi][3]);
                #pragma unroll
                for (int mi = 0; mi < 4; mi++)
                    #pragma unroll
                    for (int nt = 0; nt < 4; nt++)
                        mma16816(acc[mi][nt], A[mi], b[nt]);
            }
            BAR_SYNC(5, NCONS);                         // G1 reads of X[buf] done

            // ---------- epilogue1: bias + silu -> H via stmatrix ----------
            {
                const uint32_t hB = xB;   // H overlays X[buf]
                const int tsel = lane >> 3, rowin = lane & 7;
                #pragma unroll
                for (int mi = 0; mi < 4; mi++) {
                    uint32_t pk[4][2];
                    #pragma unroll
                    for (int ni = 0; ni < 4; ni++) {
                        const int c = nw * 32 + ni * 8 + tc;
                        float2 bb = *(const float2*)(b1 + c);
                        float v[4];
                        v[0] = acc[mi][ni][0] + bb.x;  v[1] = acc[mi][ni][1] + bb.y;
                        v[2] = acc[mi][ni][2] + bb.x;  v[3] = acc[mi][ni][3] + bb.y;
                        #pragma unroll
                        for (int q = 0; q < 4; q++) v[q] = v[q] / (1.f + __expf(-v[q]));
                        __half h0 = __float2half_rn(v[0]), h1 = __float2half_rn(v[1]);
                        __half h2 = __float2half_rn(v[2]), h3 = __float2half_rn(v[3]);
                        pk[ni][0] = (uint32_t)__half_as_ushort(h0) | ((uint32_t)__half_as_ushort(h1) << 16);
                        pk[ni][1] = (uint32_t)__half_as_ushort(h2) | ((uint32_t)__half_as_ushort(h3) << 16);
                    }
                    // two stmatrix.x4: tiles (ni_pair base np): {(np,rh0),(np,rh1),(np+1,rh0),(np+1,rh1)}
                    #pragma unroll
                    for (int np = 0; np < 2; np++) {
                        const int ni_t = np * 2 + (tsel >> 1);
                        const int rh_t = tsel & 1;
                        const int row  = mw * 64 + mi * 16 + rh_t * 8 + rowin;
                        const int col  = nw * 32 + ni_t * 8;
                        uint32_t addr = hB + (uint32_t)((row * HSTR + col) * 2);
                        stsm4(addr, pk[np*2][0], pk[np*2][1], pk[np*2+1][0], pk[np*2+1][1]);
                    }
                }
            }
            BAR_SYNC(6, NCONS);                         // H visible

            // ---------- GEMM2: 128 x 96 x 128 (this warp: 64 x 24) ----------
            float acc2[4][3][4] = {};
            for (int ks = 0; ks < 8; ks++) {
                const int k0 = ks * 16;
                uint32_t b[3][2];
                ldsm4t(w2B + (uint32_t)(((k0 + lr) * W2STR + nw * 24 + lc) * 2),
                       b[0][0], b[0][1], b[1][0], b[1][1]);
                ldsm2t(w2B + (uint32_t)(((k0 + lr) * W2STR + nw * 24 + 16) * 2),
                       b[2][0], b[2][1]);
                uint32_t A[4][4];
                #pragma unroll
                for (int mi = 0; mi < 4; mi++)
                    ldsm4(xB + (uint32_t)(((mw * 64 + mi * 16 + lr) * HSTR + k0 + lc) * 2),
                          A[mi][0], A[mi][1], A[mi][2], A[mi][3]);
                #pragma unroll
                for (int mi = 0; mi < 4; mi++)
                    #pragma unroll
                    for (int nt = 0; nt < 3; nt++)
                        mma16816(acc2[mi][nt], A[mi], b[nt]);
            }

            // ---------- epilogue2: bias + forward rotate + scatter ----------
            #pragma unroll
            for (int mi = 0; mi < 4; mi++) {
                const int rr = mw * 64 + mi * 16 + g;
                #pragma unroll
                for (int rh = 0; rh < 2; rh++) {
                    const int r = rr + rh * 8;
                    const int e = base + r;
                    if (e < E) {
                        const int nidx = sDst[buf * ET + r];
                        #pragma unroll
                        for (int ni = 0; ni < 3; ni++) {
                            const int c = nw * 24 + ni * 8 + tc;
                            float2 bb = *(const float2*)(b2 + c);
                            float m0 = acc2[mi][ni][rh*2]   + bb.x;
                            float m1 = acc2[mi][ni][rh*2+1] + bb.y;
                            if (c < 32) {
                                red2(outS + (size_t)nidx * 32 + c, m0, m1);
                            } else {
                                const int p = (c - 32) >> 1;
                                const int k = p & 3;
                                float4 R = *(const float4*)(rot + (size_t)e * 16 + k * 4);
                                red2(outR + (size_t)nidx * 64 + 2 * p,
                                     m0 * R.x + m1 * R.z, m0 * R.y + m1 * R.w);
                            }
                        }
                    }
                }
            }
            BAR_ARRIVE(3 + buf, NTHR);                  // release EMPTY[buf]
        }
    }
}

extern "C" void kernel_launch(void* const* d_in, const int* in_sizes, int n_in,
                              void* d_out, int out_size)
{
    const float* xs   = (const float*)d_in[0];
    const float* xr   = (const float*)d_in[1];
    const int*   ei   = (const int*)  d_in[2];
    const float* dist = (const float*)d_in[3];
    const float* rot  = (const float*)d_in[4];
    const float* W1   = (const float*)d_in[5];
    const float* b1   = (const float*)d_in[6];
    const float* W2   = (const float*)d_in[7];
    const float* b2   = (const float*)d_in[8];

    const int N = in_sizes[0] / 32;
    const int E = in_sizes[2] / 2;
    const int n_tiles = (E + ET - 1) / ET;

    float* outS = (float*)d_out;
    float* outR = outS + (size_t)N * 32;

    cudaMemsetAsync(d_out, 0, (size_t)out_size * sizeof(float), 0);
    cudaFuncSetAttribute(eq_main, cudaFuncAttributeMaxDynamicSharedMemorySize, SMEMB);
    int grid = n_tiles < 148 ? n_tiles : 148;
    eq_main<<<grid, NTHR, SMEMB>>>(xs, xr, ei, dist, rot, W1, b1, W2, b2,
                                   outS, outR, E, n_tiles);
}

// round 10
// speedup vs baseline: 1.1745x; 1.1745x over previous
#include <cuda_runtime.h>
#include <cuda_fp16.h>
#include <cstdint>

#define NTHR  640     // 512 consumer + 128 producer
#define NCONS 512
#define ET    128
#define XSTR  264     // halves
#define W1STR 136
#define W2STR 96
#define HSTR  136
// byte offsets in dynamic smem
#define B_X0  0            // 67584
#define B_X1  67584        // 67584
#define B_W1  135168       // 69632
#define B_W2  204800       // 24576
#define B_DST 229376       // 1024
#define B_B1  230400       // 512
#define B_B2  230912       // 384+pad
#define SMEMB 231424

// named barrier ids: FULL0=1 FULL1=2 EMPTY0=3 EMPTY1=4 C1=5 C2=6
#define BAR_SYNC(id, cnt)   asm volatile("bar.sync %0, %1;"   :: "r"(id), "r"(cnt) : "memory")
#define BAR_ARRIVE(id, cnt) asm volatile("bar.arrive %0, %1;" :: "r"(id), "r"(cnt) : "memory")

__device__ __forceinline__ uint32_t s2u(const void* p) {
    uint32_t a; asm("{ .reg .u64 t; cvta.to.shared.u64 t, %1; cvt.u32.u64 %0, t; }" : "=r"(a) : "l"(p)); return a;
}
__device__ __forceinline__ void ldsm4(uint32_t a, uint32_t& r0, uint32_t& r1, uint32_t& r2, uint32_t& r3) {
    asm volatile("ldmatrix.sync.aligned.m8n8.x4.shared.b16 {%0,%1,%2,%3}, [%4];"
                 : "=r"(r0), "=r"(r1), "=r"(r2), "=r"(r3) : "r"(a));
}
__device__ __forceinline__ void ldsm4t(uint32_t a, uint32_t& r0, uint32_t& r1, uint32_t& r2, uint32_t& r3) {
    asm volatile("ldmatrix.sync.aligned.m8n8.x4.trans.shared.b16 {%0,%1,%2,%3}, [%4];"
                 : "=r"(r0), "=r"(r1), "=r"(r2), "=r"(r3) : "r"(a));
}
__device__ __forceinline__ void ldsm2t(uint32_t a, uint32_t& r0, uint32_t& r1) {
    asm volatile("ldmatrix.sync.aligned.m8n8.x2.trans.shared.b16 {%0,%1}, [%2];"
                 : "=r"(r0), "=r"(r1) : "r"(a));
}
__device__ __forceinline__ void stsm4(uint32_t a, uint32_t r0, uint32_t r1, uint32_t r2, uint32_t r3) {
    asm volatile("stmatrix.sync.aligned.m8n8.x4.shared.b16 [%0], {%1,%2,%3,%4};"
                 :: "r"(a), "r"(r0), "r"(r1), "r"(r2), "r"(r3) : "memory");
}
__device__ __forceinline__ void mma16816(float* c, const uint32_t* a, const uint32_t* b) {
    asm volatile("mma.sync.aligned.m16n8k16.row.col.f32.f16.f16.f32 "
                 "{%0,%1,%2,%3}, {%4,%5,%6,%7}, {%8,%9}, {%0,%1,%2,%3};"
                 : "+f"(c[0]), "+f"(c[1]), "+f"(c[2]), "+f"(c[3])
                 : "r"(a[0]), "r"(a[1]), "r"(a[2]), "r"(a[3]), "r"(b[0]), "r"(b[1]));
}
__device__ __forceinline__ void red2(float* p, float a, float b) {
    asm volatile("red.global.add.v2.f32 [%0], {%1,%2};" :: "l"(p), "f"(a), "f"(b) : "memory");
}
// 8 fp32 -> 8 fp16, one 16B STS
__device__ __forceinline__ void wr8h(__half* px, int idx, const float* v) {
    uint4 u;
    uint32_t* w = (uint32_t*)&u;
    #pragma unroll
    for (int q = 0; q < 4; q++) {
        __half h0 = __float2half_rn(v[2*q]), h1 = __float2half_rn(v[2*q+1]);
        w[q] = (uint32_t)__half_as_ushort(h0) | ((uint32_t)__half_as_ushort(h1) << 16);
    }
    *(uint4*)(px + idx) = u;
}
// inverse-rotate one rep (8 values)
__device__ __forceinline__ void rot8(const float* p, const float4* rk, float* o) {
    #pragma unroll
    for (int k = 0; k < 4; k++) {
        float x0 = p[2*k], x1 = p[2*k+1];
        o[2*k]   = x0 * rk[k].x + x1 * rk[k].y;
        o[2*k+1] = x0 * rk[k].z + x1 * rk[k].w;
    }
}

__global__ __launch_bounds__(NTHR, 1)
void eq_main(const float* __restrict__ xs, const float* __restrict__ xr,
             const int* __restrict__ ei, const float* __restrict__ dist,
             const float* __restrict__ rot,
             const float* __restrict__ W1, const float* __restrict__ b1,
             const float* __restrict__ W2, const float* __restrict__ b2,
             float* __restrict__ outS, float* __restrict__ outR,
             int E, int n_tiles)
{
    extern __shared__ __align__(16) unsigned char dyn[];
    const uint32_t sb = s2u(dyn);
    __half* sW1 = (__half*)(dyn + B_W1);
    __half* sW2 = (__half*)(dyn + B_W2);
    int*   sDst = (int*)  (dyn + B_DST);
    float* sB1  = (float*)(dyn + B_B1);
    float* sB2  = (float*)(dyn + B_B2);

    const int tid = threadIdx.x, lane = tid & 31, wid = tid >> 5;

    // ---- stage weights + biases once (all threads) ----
    for (int i = tid; i < 256 * 128; i += NTHR) {
        int k = i >> 7, n = i & 127;
        sW1[k * W1STR + n] = __float2half_rn(W1[i]);
    }
    for (int i = tid; i < 128 * 96; i += NTHR) {
        int k = i / 96, n = i - k * 96;
        sW2[k * W2STR + n] = __float2half_rn(W2[i]);
    }
    if (tid < 128) sB1[tid] = b1[tid];
    else if (tid < 224) sB2[tid - 128] = b2[tid - 128];
    __syncthreads();

    const int t0 = blockIdx.x, gstride = gridDim.x;

    if (wid >= 16) {
        // ================= PRODUCER: 4 warps, 1 thread per edge =================
        const int pe = tid - NCONS;      // 0..127
        int i = 0;
        for (int t = t0; t < n_tiles; t += gstride, i++) {
            const int buf = i & 1;
            if (i >= 2) BAR_SYNC(3 + buf, NTHR);        // wait EMPTY[buf]
            __half* X = (__half*)(dyn + (buf ? B_X1 : B_X0));
            const int base = t * ET;
            const int e  = base + pe;
            const int ec = (e < E) ? e : (E - 1);
            const int srcn = ei[ec], dstn = ei[E + ec];
            sDst[buf * ET + pe] = dstn;
            float4 rk[4];
            #pragma unroll
            for (int k = 0; k < 4; k++) rk[k] = *(const float4*)(rot + (size_t)ec * 16 + k * 4);
            const int rb = pe * XSTR;
            float tmp[8], in[8];
            // x_scalar dst -> cols 0..31
            #pragma unroll
            for (int q = 0; q < 4; q++) {
                *(float4*)(tmp)     = *(const float4*)(xs + (size_t)dstn * 32 + q * 8);
                *(float4*)(tmp + 4) = *(const float4*)(xs + (size_t)dstn * 32 + q * 8 + 4);
                wr8h(X, rb + q * 8, tmp);
            }
            // x_rot dst rotated -> cols 32..95
            #pragma unroll
            for (int j = 0; j < 8; j++) {
                *(float4*)(in)     = *(const float4*)(xr + (size_t)dstn * 64 + j * 8);
                *(float4*)(in + 4) = *(const float4*)(xr + (size_t)dstn * 64 + j * 8 + 4);
                rot8(in, rk, tmp);
                wr8h(X, rb + 32 + j * 8, tmp);
            }
            // x_scalar src -> cols 96..127
            #pragma unroll
            for (int q = 0; q < 4; q++) {
                *(float4*)(tmp)     = *(const float4*)(xs + (size_t)srcn * 32 + q * 8);
                *(float4*)(tmp + 4) = *(const float4*)(xs + (size_t)srcn * 32 + q * 8 + 4);
                wr8h(X, rb + 96 + q * 8, tmp);
            }
            // x_rot src rotated -> cols 128..191
            #pragma unroll
            for (int j = 0; j < 8; j++) {
                *(float4*)(in)     = *(const float4*)(xr + (size_t)srcn * 64 + j * 8);
                *(float4*)(in + 4) = *(const float4*)(xr + (size_t)srcn * 64 + j * 8 + 4);
                rot8(in, rk, tmp);
                wr8h(X, rb + 128 + j * 8, tmp);
            }
            // distance embedding -> cols 192..255
            #pragma unroll
            for (int q = 0; q < 8; q++) {
                *(float4*)(tmp)     = *(const float4*)(dist + (size_t)ec * 64 + q * 8);
                *(float4*)(tmp + 4) = *(const float4*)(dist + (size_t)ec * 64 + q * 8 + 4);
                wr8h(X, rb + 192 + q * 8, tmp);
            }
            BAR_ARRIVE(1 + buf, NTHR);                  // signal FULL[buf]
        }
    } else {
        // ================= CONSUMER: 16 warps, warp tile 32 x 32 =================
        const int mw = wid >> 2, nw = wid & 3;
        const int lr = lane & 15, lc = (lane >> 4) << 3;
        const int g  = lane >> 2, tc = (lane & 3) * 2;
        const uint32_t w1B = sb + B_W1, w2B = sb + B_W2;

        int i = 0;
        for (int t = t0; t < n_tiles; t += gstride, i++) {
            const int buf = i & 1;
            const int base = t * ET;
            const uint32_t xB = sb + (buf ? B_X1 : B_X0);

            BAR_SYNC(1 + buf, NTHR);                    // wait FULL[buf]

            // ---------- GEMM1: 128 x 128 x 256 ----------
            float acc[2][4][4] = {};
            #pragma unroll 2
            for (int ks = 0; ks < 16; ks++) {
                const int k0 = ks * 16;
                uint32_t b[4][2];
                ldsm4t(w1B + (uint32_t)(((k0 + lr) * W1STR + nw * 32 + lc) * 2),
                       b[0][0], b[0][1], b[1][0], b[1][1]);
                ldsm4t(w1B + (uint32_t)(((k0 + lr) * W1STR + nw * 32 + 16 + lc) * 2),
                       b[2][0], b[2][1], b[3][0], b[3][1]);
                uint32_t A[2][4];
                #pragma unroll
                for (int mi = 0; mi < 2; mi++)
                    ldsm4(xB + (uint32_t)(((mw * 32 + mi * 16 + lr) * XSTR + k0 + lc) * 2),
                          A[mi][0], A[mi][1], A[mi][2], A[mi][3]);
                #pragma unroll
                for (int mi = 0; mi < 2; mi++)
                    #pragma unroll
                    for (int nt = 0; nt < 4; nt++)
                        mma16816(acc[mi][nt], A[mi], b[nt]);
            }
            BAR_SYNC(5, NCONS);                         // G1 reads of X[buf] done

            // ---------- epilogue1: bias + silu -> H via stmatrix ----------
            {
                const uint32_t hB = xB;   // H overlays X[buf]
                const int tsel = lane >> 3, rowin = lane & 7;
                #pragma unroll
                for (int mi = 0; mi < 2; mi++) {
                    uint32_t pk[4][2];
                    #pragma unroll
                    for (int ni = 0; ni < 4; ni++) {
                        const int c = nw * 32 + ni * 8 + tc;
                        float2 bb = *(const float2*)(sB1 + c);
                        float v[4];
                        v[0] = acc[mi][ni][0] + bb.x;  v[1] = acc[mi][ni][1] + bb.y;
                        v[2] = acc[mi][ni][2] + bb.x;  v[3] = acc[mi][ni][3] + bb.y;
                        #pragma unroll
                        for (int q = 0; q < 4; q++) v[q] = v[q] / (1.f + __expf(-v[q]));
                        __half h0 = __float2half_rn(v[0]), h1 = __float2half_rn(v[1]);
                        __half h2 = __float2half_rn(v[2]), h3 = __float2half_rn(v[3]);
                        pk[ni][0] = (uint32_t)__half_as_ushort(h0) | ((uint32_t)__half_as_ushort(h1) << 16);
                        pk[ni][1] = (uint32_t)__half_as_ushort(h2) | ((uint32_t)__half_as_ushort(h3) << 16);
                    }
                    #pragma unroll
                    for (int np = 0; np < 2; np++) {
                        const int ni_t = np * 2 + (tsel >> 1);
                        const int rh_t = tsel & 1;
                        const int row  = mw * 32 + mi * 16 + rh_t * 8 + rowin;
                        const int col  = nw * 32 + ni_t * 8;
                        uint32_t addr = hB + (uint32_t)((row * HSTR + col) * 2);
                        stsm4(addr, pk[np*2][0], pk[np*2][1], pk[np*2+1][0], pk[np*2+1][1]);
                    }
                }
            }
            BAR_SYNC(6, NCONS);                         // H visible

            // ---------- GEMM2: 128 x 96 x 128 ----------
            float acc2[2][3][4] = {};
            #pragma unroll 2
            for (int ks = 0; ks < 8; ks++) {
                const int k0 = ks * 16;
                uint32_t b[3][2];
                ldsm4t(w2B + (uint32_t)(((k0 + lr) * W2STR + nw * 24 + lc) * 2),
                       b[0][0], b[0][1], b[1][0], b[1][1]);
                ldsm2t(w2B + (uint32_t)(((k0 + lr) * W2STR + nw * 24 + 16) * 2),
                       b[2][0], b[2][1]);
                uint32_t A[2][4];
                #pragma unroll
                for (int mi = 0; mi < 2; mi++)
                    ldsm4(xB + (uint32_t)(((mw * 32 + mi * 16 + lr) * HSTR + k0 + lc) * 2),
                          A[mi][0], A[mi][1], A[mi][2], A[mi][3]);
                #pragma unroll
                for (int mi = 0; mi < 2; mi++)
                    #pragma unroll
                    for (int nt = 0; nt < 3; nt++)
                        mma16816(acc2[mi][nt], A[mi], b[nt]);
            }

            // ---------- epilogue2: bias + forward rotate + scatter ----------
            #pragma unroll
            for (int mi = 0; mi < 2; mi++) {
                const int rr = mw * 32 + mi * 16 + g;
                #pragma unroll
                for (int rh = 0; rh < 2; rh++) {
                    const int r = rr + rh * 8;
                    const int e = base + r;
                    if (e < E) {
                        const int nidx = sDst[buf * ET + r];
                        #pragma unroll
                        for (int ni = 0; ni < 3; ni++) {
                            const int c = nw * 24 + ni * 8 + tc;
                            float2 bb = *(const float2*)(sB2 + c);
                            float m0 = acc2[mi][ni][rh*2]   + bb.x;
                            float m1 = acc2[mi][ni][rh*2+1] + bb.y;
                            if (c < 32) {
                                red2(outS + (size_t)nidx * 32 + c, m0, m1);
                            } else {
                                const int p = (c - 32) >> 1;
                                const int k = p & 3;
                                float4 R = *(const float4*)(rot + (size_t)e * 16 + k * 4);
                                red2(outR + (size_t)nidx * 64 + 2 * p,
                                     m0 * R.x + m1 * R.z, m0 * R.y + m1 * R.w);
                            }
                        }
                    }
                }
            }
            BAR_ARRIVE(3 + buf, NTHR);                  // release EMPTY[buf]
        }
    }
}

extern "C" void kernel_launch(void* const* d_in, const int* in_sizes, int n_in,
                              void* d_out, int out_size)
{
    const float* xs   = (const float*)d_in[0];
    const float* xr   = (const float*)d_in[1];
    const int*   ei   = (const int*)  d_in[2];
    const float* dist = (const float*)d_in[3];
    const float* rot  = (const float*)d_in[4];
    const float* W1   = (const float*)d_in[5];
    const float* b1   = (const float*)d_in[6];
    const float* W2   = (const float*)d_in[7];
    const float* b2   = (const float*)d_in[8];

    const int N = in_sizes[0] / 32;
    const int E = in_sizes[2] / 2;
    const int n_tiles = (E + ET - 1) / ET;

    float* outS = (float*)d_out;
    float* outR = outS + (size_t)N * 32;

    cudaMemsetAsync(d_out, 0, (size_t)out_size * sizeof(float), 0);
    cudaFuncSetAttribute(eq_main, cudaFuncAttributeMaxDynamicSharedMemorySize, SMEMB);
    int grid = n_tiles < 148 ? n_tiles : 148;
    eq_main<<<grid, NTHR, SMEMB>>>(xs, xr, ei, dist, rot, W1, b1, W2, b2,
                                   outS, outR, E, n_tiles);
}

// round 11
// speedup vs baseline: 1.4051x; 1.1964x over previous
#include <cuda_runtime.h>
#include <cuda_fp16.h>
#include <cstdint>

#define NTHR  640     // 512 consumer + 128 producer
#define NCONS 512
#define ET    128
#define XSTR  264     // halves
#define W1STR 136
#define W2STR 96
#define HSTR  136
// byte offsets in dynamic smem
#define B_X0  0            // 67584
#define B_X1  67584        // 67584
#define B_W1  135168       // 69632
#define B_W2  204800       // 24576
#define B_DST 229376       // 1024
#define B_B1  230400       // 512
#define B_B2  230912       // 384+pad
#define SMEMB 231424

// named barrier ids: FULL0=1 FULL1=2 EMPTY0=3 EMPTY1=4 C1=5 C2=6
#define BAR_SYNC(id, cnt)   asm volatile("bar.sync %0, %1;"   :: "r"(id), "r"(cnt) : "memory")
#define BAR_ARRIVE(id, cnt) asm volatile("bar.arrive %0, %1;" :: "r"(id), "r"(cnt) : "memory")

__device__ __forceinline__ uint32_t s2u(const void* p) {
    uint32_t a; asm("{ .reg .u64 t; cvta.to.shared.u64 t, %1; cvt.u32.u64 %0, t; }" : "=r"(a) : "l"(p)); return a;
}
__device__ __forceinline__ void ldsm4(uint32_t a, uint32_t& r0, uint32_t& r1, uint32_t& r2, uint32_t& r3) {
    asm volatile("ldmatrix.sync.aligned.m8n8.x4.shared.b16 {%0,%1,%2,%3}, [%4];"
                 : "=r"(r0), "=r"(r1), "=r"(r2), "=r"(r3) : "r"(a));
}
__device__ __forceinline__ void ldsm4t(uint32_t a, uint32_t& r0, uint32_t& r1, uint32_t& r2, uint32_t& r3) {
    asm volatile("ldmatrix.sync.aligned.m8n8.x4.trans.shared.b16 {%0,%1,%2,%3}, [%4];"
                 : "=r"(r0), "=r"(r1), "=r"(r2), "=r"(r3) : "r"(a));
}
__device__ __forceinline__ void ldsm2t(uint32_t a, uint32_t& r0, uint32_t& r1) {
    asm volatile("ldmatrix.sync.aligned.m8n8.x2.trans.shared.b16 {%0,%1}, [%2];"
                 : "=r"(r0), "=r"(r1) : "r"(a));
}
__device__ __forceinline__ void stsm4(uint32_t a, uint32_t r0, uint32_t r1, uint32_t r2, uint32_t r3) {
    asm volatile("stmatrix.sync.aligned.m8n8.x4.shared.b16 [%0], {%1,%2,%3,%4};"
                 :: "r"(a), "r"(r0), "r"(r1), "r"(r2), "r"(r3) : "memory");
}
__device__ __forceinline__ void mma16816(float* c, const uint32_t* a, const uint32_t* b) {
    asm volatile("mma.sync.aligned.m16n8k16.row.col.f32.f16.f16.f32 "
                 "{%0,%1,%2,%3}, {%4,%5,%6,%7}, {%8,%9}, {%0,%1,%2,%3};"
                 : "+f"(c[0]), "+f"(c[1]), "+f"(c[2]), "+f"(c[3])
                 : "r"(a[0]), "r"(a[1]), "r"(a[2]), "r"(a[3]), "r"(b[0]), "r"(b[1]));
}
__device__ __forceinline__ void red2(float* p, float a, float b) {
    asm volatile("red.global.add.v2.f32 [%0], {%1,%2};" :: "l"(p), "f"(a), "f"(b) : "memory");
}
// 8 fp32 -> 8 fp16, one 16B STS
__device__ __forceinline__ void wr8h(__half* px, int idx, const float* v) {
    uint4 u;
    uint32_t* w = (uint32_t*)&u;
    #pragma unroll
    for (int q = 0; q < 4; q++) {
        __half h0 = __float2half_rn(v[2*q]), h1 = __float2half_rn(v[2*q+1]);
        w[q] = (uint32_t)__half_as_ushort(h0) | ((uint32_t)__half_as_ushort(h1) << 16);
    }
    *(uint4*)(px + idx) = u;
}
// inverse-rotate one rep (8 values)
__device__ __forceinline__ void rot8(const float* p, const float4* rk, float* o) {
    #pragma unroll
    for (int k = 0; k < 4; k++) {
        float x0 = p[2*k], x1 = p[2*k+1];
        o[2*k]   = x0 * rk[k].x + x1 * rk[k].y;
        o[2*k+1] = x0 * rk[k].z + x1 * rk[k].w;
    }
}

__global__ __launch_bounds__(NTHR, 1)
void eq_main(const float* __restrict__ xs, const float* __restrict__ xr,
             const int* __restrict__ ei, const float* __restrict__ dist,
             const float* __restrict__ rot,
             const float* __restrict__ W1, const float* __restrict__ b1,
             const float* __restrict__ W2, const float* __restrict__ b2,
             float* __restrict__ outS, float* __restrict__ outR,
             int E, int n_tiles)
{
    extern __shared__ __align__(16) unsigned char dyn[];
    const uint32_t sb = s2u(dyn);
    __half* sW1 = (__half*)(dyn + B_W1);
    __half* sW2 = (__half*)(dyn + B_W2);
    int*   sDst = (int*)  (dyn + B_DST);
    float* sB1  = (float*)(dyn + B_B1);
    float* sB2  = (float*)(dyn + B_B2);

    const int tid = threadIdx.x, lane = tid & 31, wid = tid >> 5;

    // ---- stage weights + biases once (all threads) ----
    for (int i = tid; i < 256 * 128; i += NTHR) {
        int k = i >> 7, n = i & 127;
        sW1[k * W1STR + n] = __float2half_rn(W1[i]);
    }
    for (int i = tid; i < 128 * 96; i += NTHR) {
        int k = i / 96, n = i - k * 96;
        sW2[k * W2STR + n] = __float2half_rn(W2[i]);
    }
    if (tid < 128) sB1[tid] = b1[tid];
    else if (tid < 224) sB2[tid - 128] = b2[tid - 128];
    __syncthreads();

    const int t0 = blockIdx.x, gstride = gridDim.x;

    if (wid >= 16) {
        // ========= PRODUCER: 4 warps, 4 threads/edge, 4 passes of 32 edges =========
        const int ptid = tid - NCONS;    // 0..127
        const int pe0  = ptid >> 2;      // 0..31 : edge within pass group
        const int s    = ptid & 3;       // quarter 0..3
        int i = 0;
        for (int t = t0; t < n_tiles; t += gstride, i++) {
            const int buf = i & 1;
            if (i >= 2) BAR_SYNC(3 + buf, NTHR);        // wait EMPTY[buf]
            __half* X = (__half*)(dyn + (buf ? B_X1 : B_X0));
            const int base = t * ET;
            #pragma unroll
            for (int pass = 0; pass < 4; pass++) {
                const int pe = pass * 32 + pe0;
                const int e  = base + pe;
                const int ec = (e < E) ? e : (E - 1);
                const int srcn = ei[ec], dstn = ei[E + ec];
                if (s == 0) sDst[buf * ET + pe] = dstn;
                float4 rk[4];
                #pragma unroll
                for (int k = 0; k < 4; k++) rk[k] = *(const float4*)(rot + (size_t)ec * 16 + k * 4);
                const int rb = pe * XSTR;
                float tmp[8], in[8];
                // x_scalar dst: thread s covers cols s*8..s*8+7
                *(float4*)(tmp)     = *(const float4*)(xs + (size_t)dstn * 32 + s * 8);
                *(float4*)(tmp + 4) = *(const float4*)(xs + (size_t)dstn * 32 + s * 8 + 4);
                wr8h(X, rb + s * 8, tmp);
                // x_scalar src -> cols 96..127
                *(float4*)(tmp)     = *(const float4*)(xs + (size_t)srcn * 32 + s * 8);
                *(float4*)(tmp + 4) = *(const float4*)(xs + (size_t)srcn * 32 + s * 8 + 4);
                wr8h(X, rb + 96 + s * 8, tmp);
                // rotated reps: thread s covers reps j = 2s, 2s+1
                #pragma unroll
                for (int jj = 0; jj < 2; jj++) {
                    const int j = 2 * s + jj;
                    *(float4*)(in)     = *(const float4*)(xr + (size_t)dstn * 64 + j * 8);
                    *(float4*)(in + 4) = *(const float4*)(xr + (size_t)dstn * 64 + j * 8 + 4);
                    rot8(in, rk, tmp);
                    wr8h(X, rb + 32 + j * 8, tmp);
                    *(float4*)(in)     = *(const float4*)(xr + (size_t)srcn * 64 + j * 8);
                    *(float4*)(in + 4) = *(const float4*)(xr + (size_t)srcn * 64 + j * 8 + 4);
                    rot8(in, rk, tmp);
                    wr8h(X, rb + 128 + j * 8, tmp);
                }
                // distance embedding: thread s covers cols 192+s*16 .. +15
                *(float4*)(tmp)     = *(const float4*)(dist + (size_t)ec * 64 + s * 16);
                *(float4*)(tmp + 4) = *(const float4*)(dist + (size_t)ec * 64 + s * 16 + 4);
                wr8h(X, rb + 192 + s * 16, tmp);
                *(float4*)(tmp)     = *(const float4*)(dist + (size_t)ec * 64 + s * 16 + 8);
                *(float4*)(tmp + 4) = *(const float4*)(dist + (size_t)ec * 64 + s * 16 + 12);
                wr8h(X, rb + 200 + s * 16, tmp);
            }
            BAR_ARRIVE(1 + buf, NTHR);                  // signal FULL[buf]
        }
    } else {
        // ================= CONSUMER: 16 warps, warp tile 32 x 32 =================
        const int mw = wid >> 2, nw = wid & 3;
        const int lr = lane & 15, lc = (lane >> 4) << 3;
        const int g  = lane >> 2, tc = (lane & 3) * 2;
        const uint32_t w1B = sb + B_W1, w2B = sb + B_W2;
        // epi2: k index is invariant across ni (ni*8 >> 1 == 0 mod 4)
        const int c0   = nw * 24 + tc;                 // first column of this thread
        const int kfix = (((c0 >= 32 ? c0 : c0 + 24) - 32) >> 1) & 3;  // valid when any c>=32

        int i = 0;
        for (int t = t0; t < n_tiles; t += gstride, i++) {
            const int buf = i & 1;
            const int base = t * ET;
            const uint32_t xB = sb + (buf ? B_X1 : B_X0);

            BAR_SYNC(1 + buf, NTHR);                    // wait FULL[buf]

            // ---------- GEMM1: 128 x 128 x 256 ----------
            float acc[2][4][4] = {};
            #pragma unroll 2
            for (int ks = 0; ks < 16; ks++) {
                const int k0 = ks * 16;
                uint32_t b[4][2];
                ldsm4t(w1B + (uint32_t)(((k0 + lr) * W1STR + nw * 32 + lc) * 2),
                       b[0][0], b[0][1], b[1][0], b[1][1]);
                ldsm4t(w1B + (uint32_t)(((k0 + lr) * W1STR + nw * 32 + 16 + lc) * 2),
                       b[2][0], b[2][1], b[3][0], b[3][1]);
                uint32_t A[2][4];
                #pragma unroll
                for (int mi = 0; mi < 2; mi++)
                    ldsm4(xB + (uint32_t)(((mw * 32 + mi * 16 + lr) * XSTR + k0 + lc) * 2),
                          A[mi][0], A[mi][1], A[mi][2], A[mi][3]);
                #pragma unroll
                for (int mi = 0; mi < 2; mi++)
                    #pragma unroll
                    for (int nt = 0; nt < 4; nt++)
                        mma16816(acc[mi][nt], A[mi], b[nt]);
            }
            BAR_SYNC(5, NCONS);                         // G1 reads of X[buf] done

            // ---------- epilogue1: bias + silu -> H via stmatrix ----------
            {
                const uint32_t hB = xB;   // H overlays X[buf]
                const int tsel = lane >> 3, rowin = lane & 7;
                #pragma unroll
                for (int mi = 0; mi < 2; mi++) {
                    uint32_t pk[4][2];
                    #pragma unroll
                    for (int ni = 0; ni < 4; ni++) {
                        const int c = nw * 32 + ni * 8 + tc;
                        float2 bb = *(const float2*)(sB1 + c);
                        float v[4];
                        v[0] = acc[mi][ni][0] + bb.x;  v[1] = acc[mi][ni][1] + bb.y;
                        v[2] = acc[mi][ni][2] + bb.x;  v[3] = acc[mi][ni][3] + bb.y;
                        #pragma unroll
                        for (int q = 0; q < 4; q++) v[q] = v[q] / (1.f + __expf(-v[q]));
                        __half h0 = __float2half_rn(v[0]), h1 = __float2half_rn(v[1]);
                        __half h2 = __float2half_rn(v[2]), h3 = __float2half_rn(v[3]);
                        pk[ni][0] = (uint32_t)__half_as_ushort(h0) | ((uint32_t)__half_as_ushort(h1) << 16);
                        pk[ni][1] = (uint32_t)__half_as_ushort(h2) | ((uint32_t)__half_as_ushort(h3) << 16);
                    }
                    #pragma unroll
                    for (int np = 0; np < 2; np++) {
                        const int ni_t = np * 2 + (tsel >> 1);
                        const int rh_t = tsel & 1;
                        const int row  = mw * 32 + mi * 16 + rh_t * 8 + rowin;
                        const int col  = nw * 32 + ni_t * 8;
                        uint32_t addr = hB + (uint32_t)((row * HSTR + col) * 2);
                        stsm4(addr, pk[np*2][0], pk[np*2][1], pk[np*2+1][0], pk[np*2+1][1]);
                    }
                }
            }
            BAR_SYNC(6, NCONS);                         // H visible

            // ---------- GEMM2: 128 x 96 x 128 ----------
            float acc2[2][3][4] = {};
            #pragma unroll 2
            for (int ks = 0; ks < 8; ks++) {
                const int k0 = ks * 16;
                uint32_t b[3][2];
                ldsm4t(w2B + (uint32_t)(((k0 + lr) * W2STR + nw * 24 + lc) * 2),
                       b[0][0], b[0][1], b[1][0], b[1][1]);
                ldsm2t(w2B + (uint32_t)(((k0 + lr) * W2STR + nw * 24 + 16) * 2),
                       b[2][0], b[2][1]);
                uint32_t A[2][4];
                #pragma unroll
                for (int mi = 0; mi < 2; mi++)
                    ldsm4(xB + (uint32_t)(((mw * 32 + mi * 16 + lr) * HSTR + k0 + lc) * 2),
                          A[mi][0], A[mi][1], A[mi][2], A[mi][3]);
                #pragma unroll
                for (int mi = 0; mi < 2; mi++)
                    #pragma unroll
                    for (int nt = 0; nt < 3; nt++)
                        mma16816(acc2[mi][nt], A[mi], b[nt]);
            }

            // ---------- epilogue2: bias + forward rotate (hoisted R) + scatter ----
            #pragma unroll
            for (int mi = 0; mi < 2; mi++) {
                const int rr = mw * 32 + mi * 16 + g;
                #pragma unroll
                for (int rh = 0; rh < 2; rh++) {
                    const int r = rr + rh * 8;
                    const int e = base + r;
                    if (e < E) {
                        const int nidx = sDst[buf * ET + r];
                        // one rot load per row (k invariant across ni); only if needed
                        float4 R;
                        if (c0 + 16 >= 32)     // this thread has at least one rot column
                            R = *(const float4*)(rot + (size_t)e * 16 + kfix * 4);
                        #pragma unroll
                        for (int ni = 0; ni < 3; ni++) {
                            const int c = nw * 24 + ni * 8 + tc;
                            float2 bb = *(const float2*)(sB2 + c);
                            float m0 = acc2[mi][ni][rh*2]   + bb.x;
                            float m1 = acc2[mi][ni][rh*2+1] + bb.y;
                            if (c < 32) {
                                red2(outS + (size_t)nidx * 32 + c, m0, m1);
                            } else {
                                red2(outR + (size_t)nidx * 64 + (c - 32),
                                     m0 * R.x + m1 * R.z, m0 * R.y + m1 * R.w);
                            }
                        }
                    }
                }
            }
            BAR_ARRIVE(3 + buf, NTHR);                  // release EMPTY[buf]
        }
    }
}

extern "C" void kernel_launch(void* const* d_in, const int* in_sizes, int n_in,
                              void* d_out, int out_size)
{
    const float* xs   = (const float*)d_in[0];
    const float* xr   = (const float*)d_in[1];
    const int*   ei   = (const int*)  d_in[2];
    const float* dist = (const float*)d_in[3];
    const float* rot  = (const float*)d_in[4];
    const float* W1   = (const float*)d_in[5];
    const float* b1   = (const float*)d_in[6];
    const float* W2   = (const float*)d_in[7];
    const float* b2   = (const float*)d_in[8];

    const int N = in_sizes[0] / 32;
    const int E = in_sizes[2] / 2;
    const int n_tiles = (E + ET - 1) / ET;

    float* outS = (float*)d_out;
    float* outR = outS + (size_t)N * 32;

    cudaMemsetAsync(d_out, 0, (size_t)out_size * sizeof(float), 0);
    cudaFuncSetAttribute(eq_main, cudaFuncAttributeMaxDynamicSharedMemorySize, SMEMB);
    int grid = n_tiles < 148 ? n_tiles : 148;
    eq_main<<<grid, NTHR, SMEMB>>>(xs, xr, ei, dist, rot, W1, b1, W2, b2,
                                   outS, outR, E, n_tiles);
}